// round 11
// baseline (speedup 1.0000x reference)
#include <cuda_runtime.h>
#include <cuda_bf16.h>

// video [B=8, C=3, T=32, H=224, W=224] fp32.
// out[b,c,t,y,x] = clip01( clamped-bilinear sample of frame (b,c,t) at
//   src = (coord + shake + 0.5) * (224/240) - 0.5 )
// (trilinear resize 224->240 has identity T axis; jax boundary weight
//  renormalization for the linear kernel == coordinate clamping.)
//
// R10: fully register-resident, zero smem, zero barriers.
//  Gather (per R9): warp's 32 columns tap a <=31-wide window -> 1 coalesced
//  LDG per lane per row + 2 __shfl_sync; h[16] horizontal lerps stay in
//  REGISTERS of the thread that owns column x.
//  Vertical pass: scale 14/15 guarantees r0(y) over 16 rows hits every
//  interval r=0..14, exactly one twice. Walk r statically (h[r], h[r+1]
//  compile-time register indices), emit 1-2 outputs per interval (uniform
//  runtime test). Coalesced scalar __stcs stores.

#define HH 224
#define WW 224
#define TT 32
#define NPLANES 768                     // B*C*T
#define TILE_Y 16
#define TILES_PER_PLANE (HH / TILE_Y)   // 14
#define THREADS 224
#define SCALE_F (14.0f / 15.0f)
#define FULLMASK 0xFFFFFFFFu

__global__ __launch_bounds__(THREADS) void shake_bilinear_reg_kernel(
    const float* __restrict__ vid,
    const int*   __restrict__ sh,
    const int*   __restrict__ sw,
    float*       __restrict__ out)
{
    int blk  = blockIdx.x;
    int tile = blk % TILES_PER_PLANE;
    int p    = blk / TILES_PER_PLANE;    // plane = (b*C + c)*T + t
    int t    = p & (TT - 1);
    int sht  = __ldg(sh + t);
    int swt  = __ldg(sw + t);
    int yb   = tile * TILE_Y;
    int tid  = threadIdx.x;

    const float* plane = vid + (long long)p * (HH * WW);

    // ---- Horizontal taps via warp-window shuffle (as R9) ----
    int   x    = tid;                    // 0..223
    int   lane = tid & 31;
    int   wx0  = tid & ~31;              // first x of this warp's strip

    float sx  = ((float)(x + swt) + 0.5f) * SCALE_F - 0.5f;
    float f0  = floorf(sx);
    float fx  = sx - f0;
    int   x0  = (int)f0;
    int   x0c = max(x0, 0);
    int   x1c = min(x0 + 1, WW - 1);

    float sxw   = ((float)(wx0 + swt) + 0.5f) * SCALE_F - 0.5f;
    int   baseX = (int)floorf(sxw);
    int   i0    = x0c - baseX;           // in [0,31]
    int   i1    = x1c - baseX;           // in [0,31]
    int   colL  = min(max(baseX + lane, 0), WW - 1);

    // Base source row for this tile (may be -1 at the top edge).
    float sy0  = ((float)(yb + sht) + 0.5f) * SCALE_F - 0.5f;
    int   base = (int)floorf(sy0);

    // ---- Gather 16 source rows, hlerp into registers h[0..15] ----
    float h[16];
#pragma unroll
    for (int w = 0; w < 2; w++) {
        float v[8];
#pragma unroll
        for (int r8 = 0; r8 < 8; r8++) {
            int srcr = min(max(base + w * 8 + r8, 0), HH - 1);
            v[r8] = __ldg(plane + srcr * WW + colL);   // coalesced LDG
        }
#pragma unroll
        for (int r8 = 0; r8 < 8; r8++) {
            float a = __shfl_sync(FULLMASK, v[r8], i0);
            float b = __shfl_sync(FULLMASK, v[r8], i1);
            h[w * 8 + r8] = fmaf(fx, b - a, a);
        }
    }

    // ---- Vertical pass: static interval walk, 16 outputs over r=0..14 ----
    float* orow = out + (long long)p * (HH * WW) + x;
    int y = 0;
#pragma unroll
    for (int r = 0; r < 15; r++) {
        // first output in interval r (always exists)
        {
            float sy = ((float)(yb + y + sht) + 0.5f) * SCALE_F - 0.5f;
            float fy = sy - floorf(sy);
            float vv = fmaf(fy, h[r + 1] - h[r], h[r]);
            __stcs(orow + (yb + y) * WW, fminf(fmaxf(vv, 0.0f), 1.0f));
            y++;
        }
        // possible second output in the same interval (uniform test)
        if (y < TILE_Y) {
            float sy = ((float)(yb + y + sht) + 0.5f) * SCALE_F - 0.5f;
            float fl = floorf(sy);
            if ((int)fl - base == r) {
                float fy = sy - fl;
                float vv = fmaf(fy, h[r + 1] - h[r], h[r]);
                __stcs(orow + (yb + y) * WW, fminf(fmaxf(vv, 0.0f), 1.0f));
                y++;
            }
        }
    }
}

extern "C" void kernel_launch(void* const* d_in, const int* in_sizes, int n_in,
                              void* d_out, int out_size)
{
    const float* vid = (const float*)d_in[0];
    const int*   sh  = (const int*)d_in[1];
    const int*   sw  = (const int*)d_in[2];
    float*       out = (float*)d_out;

    int blocks = NPLANES * TILES_PER_PLANE; // 10752
    shake_bilinear_reg_kernel<<<blocks, THREADS>>>(vid, sh, sw, out);
}

// round 12
// speedup vs baseline: 1.1089x; 1.1089x over previous
#include <cuda_runtime.h>
#include <cuda_bf16.h>

// video [B=8, C=3, T=32, H=224, W=224] fp32.
// out[b,c,t,y,x] = clip01( clamped-bilinear sample of frame (b,c,t) at
//   src = (coord + shake + 0.5) * (224/240) - 0.5 )
// (trilinear resize 224->240 has identity T axis; jax boundary weight
//  renormalization for the linear kernel == coordinate clamping.)
//
// R11: zero-smem register kernel with branch-free static epilogue.
//  Gather (R9/R10): warp's 32 columns tap a <=31-wide window -> 1 coalesced
//  LDG per lane per row + 2 __shfl_sync; h[0..15] in registers.
//  Epilogue: for y in 0..15, r0(y)-base is provably y or y-1 (scale 14/15,
//  margins ~1/30 >> fp32 noise), so the register pair (h[r0], h[r0+1]) is
//  selected with ONE predicate + two FSELs at compile-time indices.
//  16 independent outputs, no serial chain, no branches, no smem, no bar.

#define HH 224
#define WW 224
#define TT 32
#define NPLANES 768                     // B*C*T
#define TILE_Y 16
#define TILES_PER_PLANE (HH / TILE_Y)   // 14
#define THREADS 224
#define SCALE_F (14.0f / 15.0f)
#define FULLMASK 0xFFFFFFFFu

__global__ __launch_bounds__(THREADS) void shake_bilinear_sel_kernel(
    const float* __restrict__ vid,
    const int*   __restrict__ sh,
    const int*   __restrict__ sw,
    float*       __restrict__ out)
{
    int blk  = blockIdx.x;
    int tile = blk % TILES_PER_PLANE;
    int p    = blk / TILES_PER_PLANE;    // plane = (b*C + c)*T + t
    int t    = p & (TT - 1);
    int sht  = __ldg(sh + t);
    int swt  = __ldg(sw + t);
    int yb   = tile * TILE_Y;
    int tid  = threadIdx.x;

    const float* plane = vid + (long long)p * (HH * WW);

    // ---- Horizontal taps via warp-window shuffle ----
    int   x    = tid;                    // 0..223
    int   lane = tid & 31;
    int   wx0  = tid & ~31;              // first x of this warp's strip

    float sx  = ((float)(x + swt) + 0.5f) * SCALE_F - 0.5f;
    float f0  = floorf(sx);
    float fx  = sx - f0;
    int   x0  = (int)f0;
    int   x0c = max(x0, 0);
    int   x1c = min(x0 + 1, WW - 1);

    float sxw   = ((float)(wx0 + swt) + 0.5f) * SCALE_F - 0.5f;
    int   baseX = (int)floorf(sxw);
    int   i0    = x0c - baseX;           // in [0,31]
    int   i1    = x1c - baseX;           // in [0,31]
    int   colL  = min(max(baseX + lane, 0), WW - 1);

    // Base source row for this tile (may be -1 at the top edge).
    float syb  = ((float)(yb + sht) + 0.5f) * SCALE_F - 0.5f;  // sy at y=0
    int   base = (int)floorf(syb);

    // ---- Gather 16 source rows, hlerp into registers h[0..15] ----
    float h[16];
#pragma unroll
    for (int w = 0; w < 2; w++) {
        float v[8];
#pragma unroll
        for (int r8 = 0; r8 < 8; r8++) {
            int srcr = min(max(base + w * 8 + r8, 0), HH - 1);
            v[r8] = __ldg(plane + srcr * WW + colL);   // coalesced LDG
        }
#pragma unroll
        for (int r8 = 0; r8 < 8; r8++) {
            float a = __shfl_sync(FULLMASK, v[r8], i0);
            float b = __shfl_sync(FULLMASK, v[r8], i1);
            h[w * 8 + r8] = fmaf(fx, b - a, a);
        }
    }

    // ---- Branch-free vertical pass: 16 independent outputs ----
    float* orow = out + (long long)p * (HH * WW) + x;

    // y = 0: idx == 0 always.
    {
        float fy = syb - floorf(syb);
        float vv = fmaf(fy, h[1] - h[0], h[0]);
        __stcs(orow + yb * WW, fminf(fmaxf(vv, 0.0f), 1.0f));
    }
#pragma unroll
    for (int y = 1; y < 15; y++) {
        float sy  = fmaf((float)y, SCALE_F, syb);
        float fl  = floorf(sy);
        float fy  = sy - fl;
        int   idx = (int)fl - base;      // y or y-1
        bool  rep = (idx != y);
        float a   = rep ? h[y - 1] : h[y];
        float b   = rep ? h[y]     : h[y + 1];
        float vv  = fmaf(fy, b - a, a);
        __stcs(orow + (yb + y) * WW, fminf(fmaxf(vv, 0.0f), 1.0f));
    }
    // y = 15: idx == 14 always (15*14/15 = 14 exactly, margin >= 1/30).
    {
        float sy = fmaf(15.0f, SCALE_F, syb);
        float fy = sy - floorf(sy);
        float vv = fmaf(fy, h[15] - h[14], h[14]);
        __stcs(orow + (yb + 15) * WW, fminf(fmaxf(vv, 0.0f), 1.0f));
    }
}

extern "C" void kernel_launch(void* const* d_in, const int* in_sizes, int n_in,
                              void* d_out, int out_size)
{
    const float* vid = (const float*)d_in[0];
    const int*   sh  = (const int*)d_in[1];
    const int*   sw  = (const int*)d_in[2];
    float*       out = (float*)d_out;

    int blocks = NPLANES * TILES_PER_PLANE; // 10752
    shake_bilinear_sel_kernel<<<blocks, THREADS>>>(vid, sh, sw, out);
}

// round 13
// speedup vs baseline: 1.1289x; 1.0180x over previous
#include <cuda_runtime.h>
#include <cuda_bf16.h>

// video [B=8, C=3, T=32, H=224, W=224] fp32.
// out[b,c,t,y,x] = clip01( clamped-bilinear sample of frame (b,c,t) at
//   src = (coord + shake + 0.5) * (224/240) - 0.5 )
// (trilinear resize 224->240 has identity T axis; jax boundary weight
//  renormalization for the linear kernel == coordinate clamping.)
//
// R12: R11 structure (zero-smem shuffle gather + select epilogue) with the
// instruction fat trimmed:
//  - Block-uniform fast path for the 12/14 interior tiles: no per-row clamp,
//    one base pointer, 16 LDGs with immediate offsets (ptxas front-batches).
//  - __saturatef for the clip (1 op vs 2).
//  - Store base hoisted; y*WW become STG immediates.

#define HH 224
#define WW 224
#define TT 32
#define NPLANES 768                     // B*C*T
#define TILE_Y 16
#define TILES_PER_PLANE (HH / TILE_Y)   // 14
#define THREADS 224
#define SCALE_F (14.0f / 15.0f)
#define FULLMASK 0xFFFFFFFFu

__global__ __launch_bounds__(THREADS) void shake_bilinear_fast_kernel(
    const float* __restrict__ vid,
    const int*   __restrict__ sh,
    const int*   __restrict__ sw,
    float*       __restrict__ out)
{
    int blk  = blockIdx.x;
    int tile = blk % TILES_PER_PLANE;
    int p    = blk / TILES_PER_PLANE;    // plane = (b*C + c)*T + t
    int t    = p & (TT - 1);
    int sht  = __ldg(sh + t);
    int swt  = __ldg(sw + t);
    int yb   = tile * TILE_Y;
    int tid  = threadIdx.x;

    const float* plane = vid + (long long)p * (HH * WW);

    // ---- Horizontal taps via warp-window shuffle ----
    int   x    = tid;                    // 0..223
    int   lane = tid & 31;
    int   wx0  = tid & ~31;              // first x of this warp's strip

    float sx  = ((float)(x + swt) + 0.5f) * SCALE_F - 0.5f;
    float f0  = floorf(sx);
    float fx  = sx - f0;
    int   x0  = (int)f0;
    int   x0c = max(x0, 0);
    int   x1c = min(x0 + 1, WW - 1);

    float sxw   = ((float)(wx0 + swt) + 0.5f) * SCALE_F - 0.5f;
    int   baseX = (int)floorf(sxw);
    int   i0    = x0c - baseX;           // in [0,31]
    int   i1    = x1c - baseX;           // in [0,31]
    int   colL  = min(max(baseX + lane, 0), WW - 1);

    // Base source row for this tile (block-uniform).
    float syb  = ((float)(yb + sht) + 0.5f) * SCALE_F - 0.5f;  // sy at y=0
    int   base = (int)floorf(syb);

    // ---- Gather 16 source rows into v[], hlerp into h[0..15] ----
    float h[16];
    if (base >= 0 && base + 15 < HH) {
        // Interior tile (12/14 of blocks): no row clamp, immediate offsets.
        const float* rp = plane + base * WW + colL;
#pragma unroll
        for (int w = 0; w < 2; w++) {
            float v[8];
#pragma unroll
            for (int r8 = 0; r8 < 8; r8++)
                v[r8] = __ldg(rp + (w * 8 + r8) * WW);
#pragma unroll
            for (int r8 = 0; r8 < 8; r8++) {
                float a = __shfl_sync(FULLMASK, v[r8], i0);
                float b = __shfl_sync(FULLMASK, v[r8], i1);
                h[w * 8 + r8] = fmaf(fx, b - a, a);
            }
        }
    } else {
        // Edge tile: clamped rows.
#pragma unroll
        for (int w = 0; w < 2; w++) {
            float v[8];
#pragma unroll
            for (int r8 = 0; r8 < 8; r8++) {
                int srcr = min(max(base + w * 8 + r8, 0), HH - 1);
                v[r8] = __ldg(plane + srcr * WW + colL);
            }
#pragma unroll
            for (int r8 = 0; r8 < 8; r8++) {
                float a = __shfl_sync(FULLMASK, v[r8], i0);
                float b = __shfl_sync(FULLMASK, v[r8], i1);
                h[w * 8 + r8] = fmaf(fx, b - a, a);
            }
        }
    }

    // ---- Branch-free vertical pass: 16 independent outputs ----
    float* orow = out + (long long)p * (HH * WW) + yb * WW + x;

    // y = 0: interval index is always 0.
    {
        float fy = syb - floorf(syb);
        float vv = fmaf(fy, h[1] - h[0], h[0]);
        __stcs(orow, __saturatef(vv));
    }
#pragma unroll
    for (int y = 1; y < 15; y++) {
        float sy  = fmaf((float)y, SCALE_F, syb);
        float fl  = floorf(sy);
        float fy  = sy - fl;
        int   idx = (int)fl - base;      // provably y or y-1
        bool  rep = (idx != y);
        float a   = rep ? h[y - 1] : h[y];
        float b   = rep ? h[y]     : h[y + 1];
        float vv  = fmaf(fy, b - a, a);
        __stcs(orow + y * WW, __saturatef(vv));
    }
    // y = 15: interval index is always 14 (margin >= 1/30 >> fp32 noise).
    {
        float sy = fmaf(15.0f, SCALE_F, syb);
        float fy = sy - floorf(sy);
        float vv = fmaf(fy, h[15] - h[14], h[14]);
        __stcs(orow + 15 * WW, __saturatef(vv));
    }
}

extern "C" void kernel_launch(void* const* d_in, const int* in_sizes, int n_in,
                              void* d_out, int out_size)
{
    const float* vid = (const float*)d_in[0];
    const int*   sh  = (const int*)d_in[1];
    const int*   sw  = (const int*)d_in[2];
    float*       out = (float*)d_out;

    int blocks = NPLANES * TILES_PER_PLANE; // 10752
    shake_bilinear_fast_kernel<<<blocks, THREADS>>>(vid, sh, sw, out);
}